// round 3
// baseline (speedup 1.0000x reference)
#include <cuda_runtime.h>
#include <cuda_bf16.h>
#include <cstdint>

#define Bsz 8
#define Dd  1024
#define Ls  1024
#define NH  8
#define DK  128
#define NEGV (-1e30f)

// -------------------- scratch (device globals; no allocation) --------------------
__device__ float g_xt[(size_t)Bsz * Ls * Dd];              // [B, L, D]   32MB
__device__ float g_q [(size_t)Bsz * NH * Ls * DK];         // [B,H,L,DK]  32MB
__device__ float g_k [(size_t)Bsz * NH * Ls * DK];         // 32MB
__device__ float g_v [(size_t)Bsz * NH * Ls * DK];         // 32MB
__device__ float g_s [(size_t)Bsz * NH * Ls * Ls];         // [B,H,L,L]  256MB
__device__ float g_hd[(size_t)Bsz * Ls * (NH * DK)];       // [B, L, H*DK] 32MB
__device__ float g_o2[(size_t)Bsz * Ls * Dd];              // [B, L, D]   32MB

// -------------------- generic tiled GEMM core --------------------
// C(64x64 tile) = A(Mx K) * B or B^T, fp32, BK=16, 256 threads, 4x4 per thread.
#define BM 64
#define BN 64
#define BKK 16

template <bool TRANSB>
__device__ __forceinline__ void gemm_core(
    const float* __restrict__ A, int lda,
    const float* __restrict__ B, int ldb,
    int Kdim, int row0, int col0,
    float acc[4][4])
{
    __shared__ float As[BKK][BM];
    __shared__ float Bs[BKK][BN];
    const int tid = threadIdx.x;
    const int tx = tid & 15;       // n direction
    const int ty = tid >> 4;       // m direction

    for (int k0 = 0; k0 < Kdim; k0 += BKK) {
        // load A tile: 64 rows x 16 cols, one float4 per thread
        {
            int r  = tid >> 2;
            int c4 = (tid & 3) * 4;
            float4 t = *(const float4*)&A[(size_t)(row0 + r) * lda + k0 + c4];
            As[c4 + 0][r] = t.x; As[c4 + 1][r] = t.y;
            As[c4 + 2][r] = t.z; As[c4 + 3][r] = t.w;
        }
        if (TRANSB) {
            // B rows are the N dimension (contract over last dim)
            int r  = tid >> 2;
            int c4 = (tid & 3) * 4;
            float4 t = *(const float4*)&B[(size_t)(col0 + r) * ldb + k0 + c4];
            Bs[c4 + 0][r] = t.x; Bs[c4 + 1][r] = t.y;
            Bs[c4 + 2][r] = t.z; Bs[c4 + 3][r] = t.w;
        } else {
            // B is K x N row-major
            int r  = tid >> 4;
            int c4 = (tid & 15) * 4;
            float4 t = *(const float4*)&B[(size_t)(k0 + r) * ldb + col0 + c4];
            Bs[r][c4 + 0] = t.x; Bs[r][c4 + 1] = t.y;
            Bs[r][c4 + 2] = t.z; Bs[r][c4 + 3] = t.w;
        }
        __syncthreads();

        #pragma unroll
        for (int kk = 0; kk < BKK; kk++) {
            float4 a4 = *(const float4*)&As[kk][ty * 4];
            float4 b4 = *(const float4*)&Bs[kk][tx * 4];
            float a[4] = {a4.x, a4.y, a4.z, a4.w};
            float b[4] = {b4.x, b4.y, b4.z, b4.w};
            #pragma unroll
            for (int i = 0; i < 4; i++)
                #pragma unroll
                for (int j = 0; j < 4; j++)
                    acc[i][j] = fmaf(a[i], b[j], acc[i][j]);
        }
        __syncthreads();
    }
}

// -------------------- transpose [B, R, C] -> [B, C, R] --------------------
__global__ void transpose_kernel(const float* __restrict__ in, float* __restrict__ out,
                                 int R, int C)
{
    __shared__ float tile[32][33];
    const int b = blockIdx.z;
    const float* ip = in  + (size_t)b * R * C;
    float*       op = out + (size_t)b * R * C;
    const int c0 = blockIdx.x * 32;
    const int r0 = blockIdx.y * 32;
    #pragma unroll
    for (int i = threadIdx.y; i < 32; i += 8)
        tile[i][threadIdx.x] = ip[(size_t)(r0 + i) * C + c0 + threadIdx.x];
    __syncthreads();
    #pragma unroll
    for (int i = threadIdx.y; i < 32; i += 8)
        op[(size_t)(c0 + i) * R + r0 + threadIdx.x] = tile[threadIdx.x][i];
}

// -------------------- QKV projection --------------------
// grid: (DK/64=2, L/64=16, 3*B*H=192). z/(B*H) selects q|k|v.
__global__ void proj_kernel(const float* __restrict__ Wq,
                            const float* __restrict__ Wk,
                            const float* __restrict__ Wv)
{
    const int z  = blockIdx.z;
    const int w  = z >> 6;            // 0,1,2
    const int bh = z & 63;
    const int b  = bh >> 3;
    const int h  = bh & 7;

    const float* W   = (w == 0) ? Wq : (w == 1) ? Wk : Wv;
    float*       out = (w == 0) ? g_q : (w == 1) ? g_k : g_v;

    const float* A = g_xt + (size_t)b * Ls * Dd;
    const float* Bm = W + (size_t)h * Dd * DK;
    float*       C = out + (size_t)bh * Ls * DK;

    const int row0 = blockIdx.y * BM;
    const int col0 = blockIdx.x * BN;

    float acc[4][4] = {};
    gemm_core<false>(A, Dd, Bm, DK, Dd, row0, col0, acc);

    const int tx = threadIdx.x & 15, ty = threadIdx.x >> 4;
    #pragma unroll
    for (int i = 0; i < 4; i++)
        #pragma unroll
        for (int j = 0; j < 4; j++)
            C[(size_t)(row0 + ty * 4 + i) * DK + col0 + tx * 4 + j] = acc[i][j];
}

// -------------------- scores = Q K^T * scale + query-mask --------------------
// grid: (L/64=16, L/64=16, B*H=64)
__global__ void scores_kernel(const float* __restrict__ mask)
{
    const int bh = blockIdx.z;
    const int b  = bh >> 3;
    const float* A  = g_q + (size_t)bh * Ls * DK;
    const float* Bm = g_k + (size_t)bh * Ls * DK;
    float*       C  = g_s + (size_t)bh * Ls * Ls;

    const int row0 = blockIdx.y * BM;   // q
    const int col0 = blockIdx.x * BN;   // k

    float acc[4][4] = {};
    gemm_core<true>(A, DK, Bm, DK, DK, row0, col0, acc);

    const float scale = 0.088388347648318447f;  // 1/sqrt(128)
    const int tx = threadIdx.x & 15, ty = threadIdx.x >> 4;
    #pragma unroll
    for (int i = 0; i < 4; i++) {
        const int q = row0 + ty * 4 + i;
        const float madd = (1.0f - mask[(size_t)b * Ls + q]) * NEGV;
        #pragma unroll
        for (int j = 0; j < 4; j++)
            C[(size_t)q * Ls + col0 + tx * 4 + j] = acc[i][j] * scale + madd;
    }
}

// -------------------- softmax over QUERY axis (per fixed key column) --------------------
// grid: (L/256=4, B*H=64), 256 threads; thread owns one key column.
__global__ void softmax_kernel()
{
    const int bh = blockIdx.y;
    const int k  = blockIdx.x * 256 + threadIdx.x;
    float* S = g_s + (size_t)bh * Ls * Ls;

    float mx = -3.4e38f;
    for (int q = 0; q < Ls; q++)
        mx = fmaxf(mx, S[(size_t)q * Ls + k]);
    float sum = 0.0f;
    for (int q = 0; q < Ls; q++)
        sum += __expf(S[(size_t)q * Ls + k] - mx);
    const float inv = 1.0f / sum;
    for (int q = 0; q < Ls; q++) {
        float e = __expf(S[(size_t)q * Ls + k] - mx) * inv;
        S[(size_t)q * Ls + k] = e;
    }
}

// -------------------- heads = attn @ V, written as [B, L, H*DK] --------------------
// grid: (DK/64=2, L/64=16, B*H=64)
__global__ void heads_kernel()
{
    const int bh = blockIdx.z;
    const int b  = bh >> 3;
    const int h  = bh & 7;
    const float* A  = g_s + (size_t)bh * Ls * Ls;
    const float* Bm = g_v + (size_t)bh * Ls * DK;
    float*       C  = g_hd + (size_t)b * Ls * (NH * DK);

    const int row0 = blockIdx.y * BM;
    const int col0 = blockIdx.x * BN;

    float acc[4][4] = {};
    gemm_core<false>(A, Ls, Bm, DK, Ls, row0, col0, acc);

    const int tx = threadIdx.x & 15, ty = threadIdx.x >> 4;
    #pragma unroll
    for (int i = 0; i < 4; i++)
        #pragma unroll
        for (int j = 0; j < 4; j++)
            C[(size_t)(row0 + ty * 4 + i) * (NH * DK) + h * DK + col0 + tx * 4 + j] = acc[i][j];
}

// -------------------- out = head @ Wo  (stored [B, L, D], transposed later) --------------------
// grid: (D/64=16, L/64=16, B=8)
__global__ void out_kernel(const float* __restrict__ Wo)
{
    const int b = blockIdx.z;
    const float* A = g_hd + (size_t)b * Ls * Dd;
    float*       C = g_o2 + (size_t)b * Ls * Dd;

    const int row0 = blockIdx.y * BM;
    const int col0 = blockIdx.x * BN;

    float acc[4][4] = {};
    gemm_core<false>(A, Dd, Wo, Dd, Dd, row0, col0, acc);

    const int tx = threadIdx.x & 15, ty = threadIdx.x >> 4;
    #pragma unroll
    for (int i = 0; i < 4; i++)
        #pragma unroll
        for (int j = 0; j < 4; j++)
            C[(size_t)(row0 + ty * 4 + i) * Dd + col0 + tx * 4 + j] = acc[i][j];
}

// -------------------- launch --------------------
extern "C" void kernel_launch(void* const* d_in, const int* in_sizes, int n_in,
                              void* d_out, int out_size)
{
    const float* x    = (const float*)d_in[0];   // [B, D, L]
    const float* mask = (const float*)d_in[1];   // [B, L]
    const float* Wq   = (const float*)d_in[2];   // [H, D, DK]
    const float* Wk   = (const float*)d_in[3];
    const float* Wv   = (const float*)d_in[4];
    const float* Wo   = (const float*)d_in[5];   // [D, H*DK]
    float* out = (float*)d_out;                  // [B, D, L]

    float* xt_ptr; cudaGetSymbolAddress((void**)&xt_ptr, g_xt);
    float* o2_ptr; cudaGetSymbolAddress((void**)&o2_ptr, g_o2);

    // 1. x [B,D,L] -> xt [B,L,D]
    {
        dim3 g(Ls / 32, Dd / 32, Bsz);
        dim3 t(32, 8);
        transpose_kernel<<<g, t>>>(x, xt_ptr, Dd, Ls);
    }
    // 2. QKV projections
    {
        dim3 g(DK / BN, Ls / BM, 3 * Bsz * NH);
        proj_kernel<<<g, 256>>>(Wq, Wk, Wv);
    }
    // 3. scores + scale + mask
    {
        dim3 g(Ls / BN, Ls / BM, Bsz * NH);
        scores_kernel<<<g, 256>>>(mask);
    }
    // 4. softmax over query axis
    {
        dim3 g(Ls / 256, Bsz * NH);
        softmax_kernel<<<g, 256>>>();
    }
    // 5. heads = attn @ V
    {
        dim3 g(DK / BN, Ls / BM, Bsz * NH);
        heads_kernel<<<g, 256>>>();
    }
    // 6. output projection
    {
        dim3 g(Dd / BN, Ls / BM, Bsz);
        out_kernel<<<g, 256>>>(Wo);
    }
    // 7. o2 [B,L,D] -> out [B,D,L]
    {
        dim3 g(Dd / 32, Ls / 32, Bsz);
        dim3 t(32, 8);
        transpose_kernel<<<g, t>>>(o2_ptr, out, Ls, Dd);
    }
}

// round 4
// speedup vs baseline: 3.0880x; 3.0880x over previous
#include <cuda_runtime.h>
#include <cuda_bf16.h>
#include <cstdint>

#define Bsz 8
#define Dd  1024
#define Ls  1024
#define NH  8
#define DK  128
#define NEGV (-1e30f)

// -------------------- scratch (device globals; no allocation) --------------------
__device__ float g_q  [(size_t)Bsz * NH * Ls * DK];        // [B,H,L,DK]  32MB
__device__ float g_k  [(size_t)Bsz * NH * Ls * DK];        // 32MB
__device__ float g_v  [(size_t)Bsz * NH * Ls * DK];        // 32MB
__device__ float g_s  [(size_t)Bsz * NH * Ls * Ls];        // [B,H,q,k]  256MB
__device__ float g_cm [(size_t)Bsz * NH * Ls];             // col max
__device__ float g_ci [(size_t)Bsz * NH * Ls];             // col 1/sum
__device__ float g_hd [(size_t)Bsz * Ls * (NH * DK)];      // [B,L,H*DK]  32MB
__device__ float g_o2 [(size_t)Bsz * Ls * Dd];             // [B,L,D]     32MB

// ==================== tf32 mma GEMM: 128x128 tile, BK=16, 256 threads ====================
#define BM 128
#define BN 128
#define BK 16
#define LDT 132   // smem row stride (uint32 units) for both As (k-major) and Bs

__device__ __forceinline__ uint32_t f2tf(float f) {
    uint32_t u;
    asm("cvt.rna.tf32.f32 %0, %1;" : "=r"(u) : "f"(f));
    return u;
}

__device__ __forceinline__ void mma_tf32(float c[4], const uint32_t a[4], const uint32_t b[2]) {
    asm volatile(
        "mma.sync.aligned.m16n8k8.row.col.f32.tf32.tf32.f32 "
        "{%0,%1,%2,%3}, {%4,%5,%6,%7}, {%8,%9}, {%0,%1,%2,%3};"
        : "+f"(c[0]), "+f"(c[1]), "+f"(c[2]), "+f"(c[3])
        : "r"(a[0]), "r"(a[1]), "r"(a[2]), "r"(a[3]), "r"(b[0]), "r"(b[1]));
}

// ---- smem tile loaders (all store tf32 bits, k-major: Ts[k][m_or_n]) ----
// AMODE: 0 = A row-major [M][lda] (contract cols); 1 = A stored [K][ldm] (contract rows);
//        2 = like 0 but val = exp(val - gm[k])
// BMODE: 0 = B row-major [K][ldb]; 1 = B stored [N][ldn] (contract cols); 2 = like 0 scaled by gi[k]

template <int AMODE>
__device__ __forceinline__ void load_A(uint32_t (*As)[LDT], const float* __restrict__ A,
                                       int lda, int row0, int k0, const float* __restrict__ gm)
{
    const int t = threadIdx.x;
    if (AMODE == 1) {
        #pragma unroll
        for (int it = 0; it < 2; it++) {
            int idx = t + it * 256;
            int k = idx >> 5, m4 = (idx & 31) << 2;
            float4 v = *(const float4*)&A[(size_t)(k0 + k) * lda + row0 + m4];
            uint4 u = { f2tf(v.x), f2tf(v.y), f2tf(v.z), f2tf(v.w) };
            *(uint4*)&As[k][m4] = u;
        }
    } else {
        #pragma unroll
        for (int it = 0; it < 2; it++) {
            int idx = t + it * 256;
            int m = idx >> 2, c4 = (idx & 3) << 2;
            float4 v = *(const float4*)&A[(size_t)(row0 + m) * lda + k0 + c4];
            if (AMODE == 2) {
                float4 g = *(const float4*)&gm[k0 + c4];
                v.x = __expf(v.x - g.x); v.y = __expf(v.y - g.y);
                v.z = __expf(v.z - g.z); v.w = __expf(v.w - g.w);
            }
            As[c4 + 0][m] = f2tf(v.x); As[c4 + 1][m] = f2tf(v.y);
            As[c4 + 2][m] = f2tf(v.z); As[c4 + 3][m] = f2tf(v.w);
        }
    }
}

template <int BMODE>
__device__ __forceinline__ void load_B(uint32_t (*Bs)[LDT], const float* __restrict__ B,
                                       int ldb, int col0, int k0, const float* __restrict__ gi)
{
    const int t = threadIdx.x;
    if (BMODE == 1) {
        #pragma unroll
        for (int it = 0; it < 2; it++) {
            int idx = t + it * 256;
            int n = idx >> 2, c4 = (idx & 3) << 2;
            float4 v = *(const float4*)&B[(size_t)(col0 + n) * ldb + k0 + c4];
            Bs[c4 + 0][n] = f2tf(v.x); Bs[c4 + 1][n] = f2tf(v.y);
            Bs[c4 + 2][n] = f2tf(v.z); Bs[c4 + 3][n] = f2tf(v.w);
        }
    } else {
        #pragma unroll
        for (int it = 0; it < 2; it++) {
            int idx = t + it * 256;
            int k = idx >> 5, n4 = (idx & 31) << 2;
            float4 v = *(const float4*)&B[(size_t)(k0 + k) * ldb + col0 + n4];
            if (BMODE == 2) {
                float s = __ldg(&gi[k0 + k]);
                v.x *= s; v.y *= s; v.z *= s; v.w *= s;
            }
            uint4 u = { f2tf(v.x), f2tf(v.y), f2tf(v.z), f2tf(v.w) };
            *(uint4*)&Bs[k][n4] = u;
        }
    }
}

// ---- full mainloop: acc[mt][nt][4], warp tile 64x32 (2x4 warp grid) ----
template <int AMODE, int BMODE>
__device__ __forceinline__ void gemm_main(
    const float* __restrict__ A, int lda,
    const float* __restrict__ B, int ldb,
    int Kdim, int row0, int col0,
    const float* __restrict__ gm, const float* __restrict__ gi,
    float acc[4][4][4])
{
    __shared__ uint32_t As[BK][LDT];
    __shared__ uint32_t Bs[BK][LDT];

    const int lane = threadIdx.x & 31;
    const int wid  = threadIdx.x >> 5;
    const int wm   = wid & 1;      // 0..1 -> 64 rows each
    const int wn   = wid >> 1;     // 0..3 -> 32 cols each
    const int r    = lane >> 2;
    const int c2   = (lane & 3) << 1;  // permuted k base within k-step

    for (int k0 = 0; k0 < Kdim; k0 += BK) {
        load_A<AMODE>(As, A, lda, row0, k0, gm);
        load_B<BMODE>(Bs, B, ldb, col0, k0, gi);
        __syncthreads();

        #pragma unroll
        for (int ks = 0; ks < 2; ks++) {
            const int kb = ks * 8 + c2;
            uint32_t af[4][4], bf[4][2];
            #pragma unroll
            for (int mt = 0; mt < 4; mt++) {
                int ms = wm * 64 + mt * 16 + r;
                af[mt][0] = As[kb][ms];
                af[mt][1] = As[kb][ms + 8];
                af[mt][2] = As[kb + 1][ms];
                af[mt][3] = As[kb + 1][ms + 8];
            }
            #pragma unroll
            for (int nt = 0; nt < 4; nt++) {
                int ns = wn * 32 + nt * 8 + r;
                bf[nt][0] = Bs[kb][ns];
                bf[nt][1] = Bs[kb + 1][ns];
            }
            #pragma unroll
            for (int mt = 0; mt < 4; mt++)
                #pragma unroll
                for (int nt = 0; nt < 4; nt++)
                    mma_tf32(acc[mt][nt], af[mt], bf[nt]);
        }
        __syncthreads();
    }
}

// ==================== kernels ====================

// proj: q/k/v[b,h,l,dk] = sum_d x[b,d,l] * W[h,d,dk]
// grid: (8 m-tiles, 8 heads, 24: z = w*8 + b)
__global__ void __launch_bounds__(256, 2)
proj_kernel(const float* __restrict__ x,
            const float* __restrict__ Wq, const float* __restrict__ Wk,
            const float* __restrict__ Wv)
{
    const int w = blockIdx.z >> 3;
    const int b = blockIdx.z & 7;
    const int h = blockIdx.y;
    const int row0 = blockIdx.x * BM;

    const float* W   = (w == 0) ? Wq : (w == 1) ? Wk : Wv;
    float*       out = (w == 0) ? g_q : (w == 1) ? g_k : g_v;

    const float* A  = x + (size_t)b * Dd * Ls;          // [D][L], contract rows
    const float* Bm = W + (size_t)h * Dd * DK;          // [D][DK]
    float*       C  = out + (size_t)(b * NH + h) * Ls * DK;

    float acc[4][4][4] = {};
    gemm_main<1, 0>(A, Ls, Bm, DK, Dd, row0, 0, nullptr, nullptr, acc);

    const int lane = threadIdx.x & 31, wid = threadIdx.x >> 5;
    const int wm = wid & 1, wn = wid >> 1;
    const int r = lane >> 2, c2 = (lane & 3) << 1;
    #pragma unroll
    for (int mt = 0; mt < 4; mt++)
        #pragma unroll
        for (int nt = 0; nt < 4; nt++) {
            int m0 = row0 + wm * 64 + mt * 16 + r;
            int n  = wn * 32 + nt * 8 + c2;
            *(float2*)&C[(size_t)m0 * DK + n]       = make_float2(acc[mt][nt][0], acc[mt][nt][1]);
            *(float2*)&C[(size_t)(m0 + 8) * DK + n] = make_float2(acc[mt][nt][2], acc[mt][nt][3]);
        }
}

// scores: S[bh,q,k] = scale * sum_d q[q,d]*k[k,d] + (1-mask[q])*NEG
// grid: (8 n-tiles(k), 8 m-tiles(q), 64 bh)
__global__ void __launch_bounds__(256, 2)
scores_kernel(const float* __restrict__ mask)
{
    const int bh = blockIdx.z;
    const int b  = bh >> 3;
    const int row0 = blockIdx.y * BM;
    const int col0 = blockIdx.x * BN;

    const float* A  = g_q + (size_t)bh * Ls * DK;   // [L][DK] normal
    const float* Bm = g_k + (size_t)bh * Ls * DK;   // [L][DK], contract cols -> trans
    float*       C  = g_s + (size_t)bh * Ls * Ls;

    float acc[4][4][4] = {};
    gemm_main<0, 1>(A, DK, Bm, DK, DK, row0, col0, nullptr, nullptr, acc);

    const float scale = 0.088388347648318447f;  // 1/sqrt(128)
    const int lane = threadIdx.x & 31, wid = threadIdx.x >> 5;
    const int wm = wid & 1, wn = wid >> 1;
    const int r = lane >> 2, c2 = (lane & 3) << 1;
    #pragma unroll
    for (int mt = 0; mt < 4; mt++) {
        int m0 = row0 + wm * 64 + mt * 16 + r;
        float md0 = (1.0f - __ldg(&mask[(size_t)b * Ls + m0]))     * NEGV;
        float md1 = (1.0f - __ldg(&mask[(size_t)b * Ls + m0 + 8])) * NEGV;
        #pragma unroll
        for (int nt = 0; nt < 4; nt++) {
            int n = col0 + wn * 32 + nt * 8 + c2;
            *(float2*)&C[(size_t)m0 * Ls + n] =
                make_float2(acc[mt][nt][0] * scale + md0, acc[mt][nt][1] * scale + md0);
            *(float2*)&C[(size_t)(m0 + 8) * Ls + n] =
                make_float2(acc[mt][nt][2] * scale + md1, acc[mt][nt][3] * scale + md1);
        }
    }
}

// column stats: per key column k -> max over q, 1/sum(exp). grid (4, 64), 256 thr
__global__ void colstats_kernel()
{
    const int bh = blockIdx.y;
    const int k  = blockIdx.x * 256 + threadIdx.x;
    const float* S = g_s + (size_t)bh * Ls * Ls;

    float mx = -3.4e38f;
    for (int q = 0; q < Ls; q++)
        mx = fmaxf(mx, S[(size_t)q * Ls + k]);
    float sum = 0.0f;
    for (int q = 0; q < Ls; q++)
        sum += __expf(S[(size_t)q * Ls + k] - mx);
    g_cm[(size_t)bh * Ls + k] = mx;
    g_ci[(size_t)bh * Ls + k] = 1.0f / sum;
}

// heads: hd[b,l,h*128+dv] = sum_k exp(S[q,k]-m[k]) * (v[k,dv]*inv[k])
// grid: (8 m-tiles, 64 bh)
__global__ void __launch_bounds__(256, 2)
heads_kernel()
{
    const int bh = blockIdx.y;
    const int b  = bh >> 3;
    const int h  = bh & 7;
    const int row0 = blockIdx.x * BM;

    const float* A  = g_s + (size_t)bh * Ls * Ls;    // [q][k] normal + exp
    const float* Bm = g_v + (size_t)bh * Ls * DK;    // [k][dv] normal + scale
    const float* gm = g_cm + (size_t)bh * Ls;
    const float* gi = g_ci + (size_t)bh * Ls;
    float*       C  = g_hd + (size_t)b * Ls * (NH * DK) + h * DK;

    float acc[4][4][4] = {};
    gemm_main<2, 2>(A, Ls, Bm, DK, Ls, row0, 0, gm, gi, acc);

    const int lane = threadIdx.x & 31, wid = threadIdx.x >> 5;
    const int wm = wid & 1, wn = wid >> 1;
    const int r = lane >> 2, c2 = (lane & 3) << 1;
    #pragma unroll
    for (int mt = 0; mt < 4; mt++)
        #pragma unroll
        for (int nt = 0; nt < 4; nt++) {
            int m0 = row0 + wm * 64 + mt * 16 + r;
            int n  = wn * 32 + nt * 8 + c2;
            *(float2*)&C[(size_t)m0 * (NH * DK) + n]       = make_float2(acc[mt][nt][0], acc[mt][nt][1]);
            *(float2*)&C[(size_t)(m0 + 8) * (NH * DK) + n] = make_float2(acc[mt][nt][2], acc[mt][nt][3]);
        }
}

// out: o2[b,l,n] = sum_j hd[b,l,j] * Wo[j,n].  grid (8 n, 8 m, 8 b)
__global__ void __launch_bounds__(256, 2)
out_kernel(const float* __restrict__ Wo)
{
    const int b = blockIdx.z;
    const int row0 = blockIdx.y * BM;
    const int col0 = blockIdx.x * BN;

    const float* A = g_hd + (size_t)b * Ls * Dd;   // [L][1024] normal
    float*       C = g_o2 + (size_t)b * Ls * Dd;

    float acc[4][4][4] = {};
    gemm_main<0, 0>(A, Dd, Wo, Dd, Dd, row0, col0, nullptr, nullptr, acc);

    const int lane = threadIdx.x & 31, wid = threadIdx.x >> 5;
    const int wm = wid & 1, wn = wid >> 1;
    const int r = lane >> 2, c2 = (lane & 3) << 1;
    #pragma unroll
    for (int mt = 0; mt < 4; mt++)
        #pragma unroll
        for (int nt = 0; nt < 4; nt++) {
            int m0 = row0 + wm * 64 + mt * 16 + r;
            int n  = col0 + wn * 32 + nt * 8 + c2;
            *(float2*)&C[(size_t)m0 * Dd + n]       = make_float2(acc[mt][nt][0], acc[mt][nt][1]);
            *(float2*)&C[(size_t)(m0 + 8) * Dd + n] = make_float2(acc[mt][nt][2], acc[mt][nt][3]);
        }
}

// transpose [B, R, C] -> [B, C, R]
__global__ void transpose_kernel(const float* __restrict__ in, float* __restrict__ out,
                                 int R, int C)
{
    __shared__ float tile[32][33];
    const int b = blockIdx.z;
    const float* ip = in  + (size_t)b * R * C;
    float*       op = out + (size_t)b * R * C;
    const int c0 = blockIdx.x * 32;
    const int r0 = blockIdx.y * 32;
    #pragma unroll
    for (int i = threadIdx.y; i < 32; i += 8)
        tile[i][threadIdx.x] = ip[(size_t)(r0 + i) * C + c0 + threadIdx.x];
    __syncthreads();
    #pragma unroll
    for (int i = threadIdx.y; i < 32; i += 8)
        op[(size_t)(c0 + i) * R + r0 + threadIdx.x] = tile[threadIdx.x][i];
}

// -------------------- launch --------------------
extern "C" void kernel_launch(void* const* d_in, const int* in_sizes, int n_in,
                              void* d_out, int out_size)
{
    const float* x    = (const float*)d_in[0];   // [B, D, L]
    const float* mask = (const float*)d_in[1];   // [B, L]
    const float* Wq   = (const float*)d_in[2];   // [H, D, DK]
    const float* Wk   = (const float*)d_in[3];
    const float* Wv   = (const float*)d_in[4];
    const float* Wo   = (const float*)d_in[5];   // [D, H*DK]
    float* out = (float*)d_out;                  // [B, D, L]

    float* o2_ptr; cudaGetSymbolAddress((void**)&o2_ptr, g_o2);

    {   // QKV projections (x read transposed in-kernel; no transpose pass)
        dim3 g(Ls / BM, NH, 3 * Bsz);
        proj_kernel<<<g, 256>>>(x, Wq, Wk, Wv);
    }
    {   // scores + scale + query-mask
        dim3 g(Ls / BN, Ls / BM, Bsz * NH);
        scores_kernel<<<g, 256>>>(mask);
    }
    {   // per-key-column softmax stats (max, 1/sum)
        dim3 g(Ls / 256, Bsz * NH);
        colstats_kernel<<<g, 256>>>();
    }
    {   // heads = softmax(S) @ V with exp+normalize fused into operand loads
        dim3 g(Ls / BM, Bsz * NH);
        heads_kernel<<<g, 256>>>();
    }
    {   // output projection
        dim3 g(Dd / BN, Ls / BM, Bsz);
        out_kernel<<<g, 256>>>(Wo);
    }
    {   // o2 [B,L,D] -> out [B,D,L]
        dim3 g(Dd / 32, Ls / 32, Bsz);
        dim3 t(32, 8);
        transpose_kernel<<<g, t>>>(o2_ptr, out, Ls, Dd);
    }
}

// round 5
// speedup vs baseline: 3.6584x; 1.1847x over previous
#include <cuda_runtime.h>
#include <cuda_bf16.h>
#include <cstdint>

#define Bsz 8
#define Dd  1024
#define Ls  1024
#define NH  8
#define DK  128
#define NEGV (-1e30f)

// -------------------- scratch (device globals; no allocation) --------------------
__device__ float g_q  [(size_t)Bsz * NH * Ls * DK];        // [B,H,L,DK]  32MB
__device__ float g_k  [(size_t)Bsz * NH * Ls * DK];        // 32MB
__device__ float g_v  [(size_t)Bsz * NH * Ls * DK];        // 32MB
__device__ float g_s  [(size_t)Bsz * NH * Ls * Ls];        // E = exp(S)  256MB
__device__ float g_ci [(size_t)Bsz * NH * Ls];             // col sums -> 1/sum
__device__ float g_hd [(size_t)Bsz * Ls * (NH * DK)];      // [B,L,H*DK]  32MB

// ==================== tf32 mma GEMM: 128x128 tile, BK=16, 256 threads ====================
#define BM 128
#define BN 128
#define BK 16
#define LDT 132   // smem row stride (uint32 units)

__device__ __forceinline__ uint32_t f2tf(float f) {
    uint32_t u;
    asm("cvt.rna.tf32.f32 %0, %1;" : "=r"(u) : "f"(f));
    return u;
}

__device__ __forceinline__ void mma_tf32(float c[4], const uint32_t a[4], const uint32_t b[2]) {
    asm volatile(
        "mma.sync.aligned.m16n8k8.row.col.f32.tf32.tf32.f32 "
        "{%0,%1,%2,%3}, {%4,%5,%6,%7}, {%8,%9}, {%0,%1,%2,%3};"
        : "+f"(c[0]), "+f"(c[1]), "+f"(c[2]), "+f"(c[3])
        : "r"(a[0]), "r"(a[1]), "r"(a[2]), "r"(a[3]), "r"(b[0]), "r"(b[1]));
}

// AMODE: 0 = A row-major [M][lda]; 1 = A stored [K][ldm] (contract rows)
// BMODE: 0 = B row-major [K][ldb]; 1 = B stored [N][ldn] (contract cols); 2 = 0 scaled by gi[k]

template <int AMODE>
__device__ __forceinline__ void ldgA(float4 r[2], const float* __restrict__ A,
                                     int lda, int row0, int k0)
{
    const int t = threadIdx.x;
    #pragma unroll
    for (int it = 0; it < 2; it++) {
        int idx = t + it * 256;
        if (AMODE == 1) {
            int k = idx >> 5, m4 = (idx & 31) << 2;
            r[it] = *(const float4*)&A[(size_t)(k0 + k) * lda + row0 + m4];
        } else {
            int m = idx >> 2, c4 = (idx & 3) << 2;
            r[it] = *(const float4*)&A[(size_t)(row0 + m) * lda + k0 + c4];
        }
    }
}

template <int AMODE>
__device__ __forceinline__ void stsA(uint32_t (*As)[LDT], const float4 r[2])
{
    const int t = threadIdx.x;
    #pragma unroll
    for (int it = 0; it < 2; it++) {
        int idx = t + it * 256;
        if (AMODE == 1) {
            int k = idx >> 5, m4 = (idx & 31) << 2;
            uint4 u = { f2tf(r[it].x), f2tf(r[it].y), f2tf(r[it].z), f2tf(r[it].w) };
            *(uint4*)&As[k][m4] = u;
        } else {
            int m = idx >> 2, c4 = (idx & 3) << 2;
            As[c4 + 0][m] = f2tf(r[it].x);
            As[c4 + 1][m] = f2tf(r[it].y);
            As[c4 + 2][m] = f2tf(r[it].z);
            As[c4 + 3][m] = f2tf(r[it].w);
        }
    }
}

template <int BMODE>
__device__ __forceinline__ void ldgB(float4 r[2], float s[2], const float* __restrict__ B,
                                     int ldb, int col0, int k0, const float* __restrict__ gi)
{
    const int t = threadIdx.x;
    #pragma unroll
    for (int it = 0; it < 2; it++) {
        int idx = t + it * 256;
        if (BMODE == 1) {
            int n = idx >> 2, c4 = (idx & 3) << 2;
            r[it] = *(const float4*)&B[(size_t)(col0 + n) * ldb + k0 + c4];
        } else {
            int k = idx >> 5, n4 = (idx & 31) << 2;
            r[it] = *(const float4*)&B[(size_t)(k0 + k) * ldb + col0 + n4];
            if (BMODE == 2) s[it] = __ldg(&gi[k0 + k]);
        }
    }
}

template <int BMODE>
__device__ __forceinline__ void stsB(uint32_t (*Bs)[LDT], const float4 r[2], const float s[2])
{
    const int t = threadIdx.x;
    #pragma unroll
    for (int it = 0; it < 2; it++) {
        int idx = t + it * 256;
        if (BMODE == 1) {
            int n = idx >> 2, c4 = (idx & 3) << 2;
            Bs[c4 + 0][n] = f2tf(r[it].x);
            Bs[c4 + 1][n] = f2tf(r[it].y);
            Bs[c4 + 2][n] = f2tf(r[it].z);
            Bs[c4 + 3][n] = f2tf(r[it].w);
        } else {
            int k = idx >> 5, n4 = (idx & 31) << 2;
            float4 v = r[it];
            if (BMODE == 2) { v.x *= s[it]; v.y *= s[it]; v.z *= s[it]; v.w *= s[it]; }
            uint4 u = { f2tf(v.x), f2tf(v.y), f2tf(v.z), f2tf(v.w) };
            *(uint4*)&Bs[k][n4] = u;
        }
    }
}

// Double-buffered mainloop. Warp tile 64x32 (2x4 warp grid), acc[4][4][4].
template <int AMODE, int BMODE>
__device__ __forceinline__ void gemm_main(
    const float* __restrict__ A, int lda,
    const float* __restrict__ B, int ldb,
    int Kdim, int row0, int col0,
    const float* __restrict__ gi,
    float acc[4][4][4])
{
    __shared__ uint32_t As[2][BK][LDT];
    __shared__ uint32_t Bs[2][BK][LDT];

    const int lane = threadIdx.x & 31;
    const int wid  = threadIdx.x >> 5;
    const int wm   = wid & 1;
    const int wn   = wid >> 1;
    const int r    = lane >> 2;
    const int c2   = (lane & 3) << 1;

    float4 ra[2], rb[2];
    float  rs[2];

    ldgA<AMODE>(ra, A, lda, row0, 0);
    ldgB<BMODE>(rb, rs, B, ldb, col0, 0, gi);
    stsA<AMODE>(As[0], ra);
    stsB<BMODE>(Bs[0], rb, rs);
    __syncthreads();

    const int nk = Kdim / BK;
    for (int i = 0; i < nk; i++) {
        const int cur = i & 1;
        if (i + 1 < nk) {
            ldgA<AMODE>(ra, A, lda, row0, (i + 1) * BK);
            ldgB<BMODE>(rb, rs, B, ldb, col0, (i + 1) * BK, gi);
        }

        #pragma unroll
        for (int ks = 0; ks < 2; ks++) {
            const int kb = ks * 8 + c2;
            uint32_t af[4][4], bf[4][2];
            #pragma unroll
            for (int mt = 0; mt < 4; mt++) {
                int ms = wm * 64 + mt * 16 + r;
                af[mt][0] = As[cur][kb][ms];
                af[mt][1] = As[cur][kb][ms + 8];
                af[mt][2] = As[cur][kb + 1][ms];
                af[mt][3] = As[cur][kb + 1][ms + 8];
            }
            #pragma unroll
            for (int nt = 0; nt < 4; nt++) {
                int ns = wn * 32 + nt * 8 + r;
                bf[nt][0] = Bs[cur][kb][ns];
                bf[nt][1] = Bs[cur][kb + 1][ns];
            }
            #pragma unroll
            for (int mt = 0; mt < 4; mt++)
                #pragma unroll
                for (int nt = 0; nt < 4; nt++)
                    mma_tf32(acc[mt][nt], af[mt], bf[nt]);
        }

        if (i + 1 < nk) {
            stsA<AMODE>(As[cur ^ 1], ra);
            stsB<BMODE>(Bs[cur ^ 1], rb, rs);
            __syncthreads();
        }
    }
}

// ==================== kernels ====================

// proj: q/k/v[b,h,l,dk] = sum_d x[b,d,l] * W[h,d,dk]
__global__ void __launch_bounds__(256, 2)
proj_kernel(const float* __restrict__ x,
            const float* __restrict__ Wq, const float* __restrict__ Wk,
            const float* __restrict__ Wv)
{
    const int w = blockIdx.z >> 3;
    const int b = blockIdx.z & 7;
    const int h = blockIdx.y;
    const int row0 = blockIdx.x * BM;

    const float* W   = (w == 0) ? Wq : (w == 1) ? Wk : Wv;
    float*       out = (w == 0) ? g_q : (w == 1) ? g_k : g_v;

    const float* A  = x + (size_t)b * Dd * Ls;
    const float* Bm = W + (size_t)h * Dd * DK;
    float*       C  = out + (size_t)(b * NH + h) * Ls * DK;

    float acc[4][4][4] = {};
    gemm_main<1, 0>(A, Ls, Bm, DK, Dd, row0, 0, nullptr, acc);

    const int lane = threadIdx.x & 31, wid = threadIdx.x >> 5;
    const int wm = wid & 1, wn = wid >> 1;
    const int r = lane >> 2, c2 = (lane & 3) << 1;
    #pragma unroll
    for (int mt = 0; mt < 4; mt++)
        #pragma unroll
        for (int nt = 0; nt < 4; nt++) {
            int m0 = row0 + wm * 64 + mt * 16 + r;
            int n  = wn * 32 + nt * 8 + c2;
            *(float2*)&C[(size_t)m0 * DK + n]       = make_float2(acc[mt][nt][0], acc[mt][nt][1]);
            *(float2*)&C[(size_t)(m0 + 8) * DK + n] = make_float2(acc[mt][nt][2], acc[mt][nt][3]);
        }
}

// scores: E[bh,q,k] = exp(scale*QK^T + (1-mask[q])*NEG); atomic col sums -> g_ci
__global__ void __launch_bounds__(256, 2)
scores_kernel(const float* __restrict__ mask)
{
    const int bh = blockIdx.z;
    const int b  = bh >> 3;
    const int row0 = blockIdx.y * BM;
    const int col0 = blockIdx.x * BN;

    const float* A  = g_q + (size_t)bh * Ls * DK;
    const float* Bm = g_k + (size_t)bh * Ls * DK;
    float*       C  = g_s + (size_t)bh * Ls * Ls;
    float*    gsum  = g_ci + (size_t)bh * Ls;

    float acc[4][4][4] = {};
    gemm_main<0, 1>(A, DK, Bm, DK, DK, row0, col0, nullptr, acc);

    const float scale = 0.088388347648318447f;  // 1/sqrt(128)
    const int lane = threadIdx.x & 31, wid = threadIdx.x >> 5;
    const int wm = wid & 1, wn = wid >> 1;
    const int r = lane >> 2, c2 = (lane & 3) << 1;

    float cs[4][2] = {};
    #pragma unroll
    for (int mt = 0; mt < 4; mt++) {
        int m0 = row0 + wm * 64 + mt * 16 + r;
        float md0 = (1.0f - __ldg(&mask[(size_t)b * Ls + m0]))     * NEGV;
        float md1 = (1.0f - __ldg(&mask[(size_t)b * Ls + m0 + 8])) * NEGV;
        #pragma unroll
        for (int nt = 0; nt < 4; nt++) {
            int n = col0 + wn * 32 + nt * 8 + c2;
            float e0 = __expf(acc[mt][nt][0] * scale + md0);
            float e1 = __expf(acc[mt][nt][1] * scale + md0);
            float e2 = __expf(acc[mt][nt][2] * scale + md1);
            float e3 = __expf(acc[mt][nt][3] * scale + md1);
            *(float2*)&C[(size_t)m0 * Ls + n]       = make_float2(e0, e1);
            *(float2*)&C[(size_t)(m0 + 8) * Ls + n] = make_float2(e2, e3);
            cs[nt][0] += e0 + e2;
            cs[nt][1] += e1 + e3;
        }
    }
    #pragma unroll
    for (int nt = 0; nt < 4; nt++) {
        int n = col0 + wn * 32 + nt * 8 + c2;
        atomicAdd(&gsum[n],     cs[nt][0]);
        atomicAdd(&gsum[n + 1], cs[nt][1]);
    }
}

// invert column sums in place
__global__ void inv_kernel()
{
    int i = blockIdx.x * 256 + threadIdx.x;
    g_ci[i] = 1.0f / g_ci[i];
}

// heads: hd[b,l,h*128+dv] = sum_k E[q,k] * (v[k,dv]*inv[k])
__global__ void __launch_bounds__(256, 2)
heads_kernel()
{
    const int bh = blockIdx.y;
    const int b  = bh >> 3;
    const int h  = bh & 7;
    const int row0 = blockIdx.x * BM;

    const float* A  = g_s + (size_t)bh * Ls * Ls;
    const float* Bm = g_v + (size_t)bh * Ls * DK;
    const float* gi = g_ci + (size_t)bh * Ls;
    float*       C  = g_hd + (size_t)b * Ls * (NH * DK) + h * DK;

    float acc[4][4][4] = {};
    gemm_main<0, 2>(A, Ls, Bm, DK, Ls, row0, 0, gi, acc);

    const int lane = threadIdx.x & 31, wid = threadIdx.x >> 5;
    const int wm = wid & 1, wn = wid >> 1;
    const int r = lane >> 2, c2 = (lane & 3) << 1;
    #pragma unroll
    for (int mt = 0; mt < 4; mt++)
        #pragma unroll
        for (int nt = 0; nt < 4; nt++) {
            int m0 = row0 + wm * 64 + mt * 16 + r;
            int n  = wn * 32 + nt * 8 + c2;
            *(float2*)&C[(size_t)m0 * (NH * DK) + n]       = make_float2(acc[mt][nt][0], acc[mt][nt][1]);
            *(float2*)&C[(size_t)(m0 + 8) * (NH * DK) + n] = make_float2(acc[mt][nt][2], acc[mt][nt][3]);
        }
}

// out: out[b, n, m] = sum_j hd[b,m,j] * Wo[j,n]  (transposed write, fused)
__global__ void __launch_bounds__(256, 2)
out_kernel(const float* __restrict__ Wo, float* __restrict__ outp)
{
    const int b = blockIdx.z;
    const int row0 = blockIdx.y * BM;
    const int col0 = blockIdx.x * BN;

    const float* A = g_hd + (size_t)b * Ls * Dd;
    float*       C = outp + (size_t)b * Dd * Ls;   // [D][L]

    float acc[4][4][4] = {};
    gemm_main<0, 0>(A, Dd, Wo, Dd, Dd, row0, col0, nullptr, acc);

    const int lane = threadIdx.x & 31, wid = threadIdx.x >> 5;
    const int wm = wid & 1, wn = wid >> 1;
    const int r = lane >> 2, c2 = (lane & 3) << 1;
    #pragma unroll
    for (int mt = 0; mt < 4; mt++) {
        int m0 = row0 + wm * 64 + mt * 16 + r;
        #pragma unroll
        for (int nt = 0; nt < 4; nt++) {
            int n = col0 + wn * 32 + nt * 8 + c2;
            C[(size_t)n * Ls + m0]           = acc[mt][nt][0];
            C[(size_t)(n + 1) * Ls + m0]     = acc[mt][nt][1];
            C[(size_t)n * Ls + m0 + 8]       = acc[mt][nt][2];
            C[(size_t)(n + 1) * Ls + m0 + 8] = acc[mt][nt][3];
        }
    }
}

// -------------------- launch --------------------
extern "C" void kernel_launch(void* const* d_in, const int* in_sizes, int n_in,
                              void* d_out, int out_size)
{
    const float* x    = (const float*)d_in[0];   // [B, D, L]
    const float* mask = (const float*)d_in[1];   // [B, L]
    const float* Wq   = (const float*)d_in[2];   // [H, D, DK]
    const float* Wk   = (const float*)d_in[3];
    const float* Wv   = (const float*)d_in[4];
    const float* Wo   = (const float*)d_in[5];   // [D, H*DK]
    float* out = (float*)d_out;                  // [B, D, L]

    float* ci_ptr; cudaGetSymbolAddress((void**)&ci_ptr, g_ci);
    cudaMemsetAsync(ci_ptr, 0, (size_t)Bsz * NH * Ls * sizeof(float), 0);

    {   // QKV projections (x read transposed in-kernel)
        dim3 g(Ls / BM, NH, 3 * Bsz);
        proj_kernel<<<g, 256>>>(x, Wq, Wk, Wv);
    }
    {   // scores -> E = exp(...), atomic column sums
        dim3 g(Ls / BN, Ls / BM, Bsz * NH);
        scores_kernel<<<g, 256>>>(mask);
    }
    {   // invert column sums
        inv_kernel<<<(Bsz * NH * Ls) / 256, 256>>>();
    }
    {   // heads = E @ (V * inv)
        dim3 g(Ls / BM, Bsz * NH);
        heads_kernel<<<g, 256>>>();
    }
    {   // output projection with fused transpose
        dim3 g(Dd / BN, Ls / BM, Bsz);
        out_kernel<<<g, 256>>>(Wo, out);
    }
}